// round 8
// baseline (speedup 1.0000x reference)
#include <cuda_runtime.h>
#include <math.h>

#define NB   8
#define CIN  16
#define HH   32
#define WW   32
#define OC   64
#define RDIM 144
#define OH   30
#define OW   30

// Packed fp32x2 ops (sm_100+), lanewise on 2 packed fp32
#define FMA2(d, a, b) \
    asm("fma.rn.f32x2 %0, %1, %2, %0;" : "+l"(d) : "l"(a), "l"(b))
#define ADD2(d, a, b) \
    asm("add.rn.f32x2 %0, %1, %2;" : "=l"(d) : "l"(a), "l"(b))
#define PACK2(d, v) \
    asm("mov.b64 %0, {%1, %1};" : "=l"(d) : "r"(__float_as_uint(v)))

__global__ __launch_bounds__(512, 1)
void fused_kernel(const float* __restrict__ x,
                  const float* __restrict__ k,
                  const float* __restrict__ bias,
                  const float* __restrict__ dxp,
                  const float* __restrict__ dwp,
                  float* __restrict__ out) {
    __shared__ float ws[RDIM][OC];    // exp(k+5): 36864 B
    __shared__ float xc[CIN][4][WW];  // clamped x+5 slab: 8192 B (reused as reduce buf)
    __shared__ float srow[4][WW];     // channel-sums of raw x: 512 B
    __shared__ float part[8][OC];     // koff partials: 2048 B
    __shared__ float koff[OC];        // 256 B
    __shared__ float sdw;
    // total ~47.9 KB < 48 KB static

    const int n  = blockIdx.y;
    const int r0 = blockIdx.x * 2;    // output row base
    const int t  = threadIdx.x;
    const int lane = t & 31;
    const int wid  = t >> 5;          // 0..15

    // --- Stage weights with fused exp; fold koff partials into same loads ---
    {
        const int oci  = t & 63;
        const int rsub = t >> 6;      // 0..7
        float ks = 0.0f;
        #pragma unroll
        for (int rb = 0; rb < RDIM; rb += 8) {
            const float kv = k[(rb + rsub) * OC + oci];
            ks += kv;
            ws[rb + rsub][oci] = expf(kv + 5.0f);
        }
        part[rsub][oci] = ks;
    }
    // --- Stage x slab (threads 0..127) ---
    if (t < 128) {
        const int srw = t >> 5, w = t & 31;
        const float* xp = x + ((size_t)n * CIN * HH + (r0 + srw)) * WW + w;
        float s = 0.0f;
        #pragma unroll
        for (int c = 0; c < CIN; c++) {
            float v = xp[(size_t)c * HH * WW];
            s += v;
            xc[c][srw][w] = fmaxf(v + 5.0f, 1e-12f);
        }
        srow[srw][w] = s;
    }
    if (t == 0) sdw = dwp[0];
    __syncthreads();
    if (t < OC) {
        float s = 0.0f;
        #pragma unroll
        for (int j = 0; j < 8; j++) s += part[j][t];
        koff[t] = bias[t] - dxp[0] * s;
    }
    __syncthreads();

    // --- Main loop: warp = (oc octet, channel half); lane = rowbit*16 + colpair ---
    const int cp    = lane & 15;             // col pair (cp==15 inactive)
    const int rowb  = lane >> 4;             // 0..1
    const int ocg   = (wid & 7) * 8;         // warp-uniform oc base
    const int cbase = (wid >> 3) * 8;        // channel half: 0 or 8
    const int c0    = (cp < 15) ? 2 * cp : 28;

    unsigned long long acc[2][4];
    #pragma unroll
    for (int j = 0; j < 2; j++)
        #pragma unroll
        for (int q = 0; q < 4; q++) acc[j][q] = 0ull;

    #pragma unroll
    for (int kh = 0; kh < 3; kh++) {
        // pipeline fill for this kh
        ulonglong2 cw[3][2];
        #pragma unroll
        for (int kw = 0; kw < 3; kw++) {
            const ulonglong2* wp =
                (const ulonglong2*)&ws[(kh * 3 + kw) * CIN + cbase][ocg];
            cw[kw][0] = wp[0];
            cw[kw][1] = wp[1];
        }
        float2 cxa = *(const float2*)&xc[cbase][rowb + kh][c0];
        float2 cxb = *(const float2*)&xc[cbase][rowb + kh][c0 + 2];

        #pragma unroll
        for (int c = 0; c < 8; c++) {
            const int cn = cbase + ((c + 1 < 8) ? c + 1 : c);
            // prefetch c+1 (weights + x) before consuming c
            ulonglong2 nw[3][2];
            #pragma unroll
            for (int kw = 0; kw < 3; kw++) {
                const ulonglong2* wp =
                    (const ulonglong2*)&ws[(kh * 3 + kw) * CIN + cn][ocg];
                nw[kw][0] = wp[0];
                nw[kw][1] = wp[1];
            }
            const float2 nxa = *(const float2*)&xc[cn][rowb + kh][c0];
            const float2 nxb = *(const float2*)&xc[cn][rowb + kh][c0 + 2];

            unsigned long long p[4];
            PACK2(p[0], cxa.x);
            PACK2(p[1], cxa.y);
            PACK2(p[2], cxb.x);
            PACK2(p[3], cxb.y);
            #pragma unroll
            for (int kw = 0; kw < 3; kw++) {
                FMA2(acc[0][0], p[kw],     cw[kw][0].x);
                FMA2(acc[0][1], p[kw],     cw[kw][0].y);
                FMA2(acc[0][2], p[kw],     cw[kw][1].x);
                FMA2(acc[0][3], p[kw],     cw[kw][1].y);
                FMA2(acc[1][0], p[kw + 1], cw[kw][0].x);
                FMA2(acc[1][1], p[kw + 1], cw[kw][0].y);
                FMA2(acc[1][2], p[kw + 1], cw[kw][1].x);
                FMA2(acc[1][3], p[kw + 1], cw[kw][1].y);
            }
            #pragma unroll
            for (int kw = 0; kw < 3; kw++) {
                cw[kw][0] = nw[kw][0];
                cw[kw][1] = nw[kw][1];
            }
            cxa = nxa;
            cxb = nxb;
        }
    }

    // --- Cross-warp reduction of channel halves (reuse xc as 8KB u64 buffer) ---
    unsigned long long* buf = (unsigned long long*)&xc[0][0][0];  // 1024 u64
    const int slot = ((wid & 7) * 32 + lane) * 2;
    __syncthreads();   // xc reads done everywhere
    #pragma unroll
    for (int j = 0; j < 2; j++) {
        if (wid >= 8) {
            buf[slot]     = acc[j][0];
            buf[slot + 1] = acc[j][1];
            buf[slot + 512]     = acc[j][2];
            buf[slot + 513] = acc[j][3];
        }
        __syncthreads();
        if (wid < 8) {
            ADD2(acc[j][0], acc[j][0], buf[slot]);
            ADD2(acc[j][1], acc[j][1], buf[slot + 1]);
            ADD2(acc[j][2], acc[j][2], buf[slot + 512]);
            ADD2(acc[j][3], acc[j][3], buf[slot + 513]);
        }
        __syncthreads();
    }

    if (wid < 8 && cp < 15) {
        float xs0 = 0.0f, xs1 = 0.0f;
        #pragma unroll
        for (int kh = 0; kh < 3; kh++)
            #pragma unroll
            for (int kw = 0; kw < 3; kw++) {
                xs0 += srow[rowb + kh][2 * cp + kw];
                xs1 += srow[rowb + kh][2 * cp + 1 + kw];
            }
        const float dwv = sdw;
        xs0 *= dwv; xs1 *= dwv;

        const int row = r0 + rowb;
        const int col = 2 * cp;
        float* op = out + ((size_t)(n * OC + ocg)) * (OH * OW) + row * OW + col;
        #pragma unroll
        for (int q = 0; q < 4; q++) {
            const float a0lo = __uint_as_float((unsigned)(acc[0][q] & 0xffffffffu));
            const float a0hi = __uint_as_float((unsigned)(acc[0][q] >> 32));
            const float a1lo = __uint_as_float((unsigned)(acc[1][q] & 0xffffffffu));
            const float a1hi = __uint_as_float((unsigned)(acc[1][q] >> 32));
            const float k0 = koff[ocg + 2 * q];
            const float k1 = koff[ocg + 2 * q + 1];
            float2 v0 = make_float2(a0lo - xs0 + k0, a1lo - xs1 + k0);
            float2 v1 = make_float2(a0hi - xs0 + k1, a1hi - xs1 + k1);
            *(float2*)(op + (size_t)(2 * q)     * (OH * OW)) = v0;
            *(float2*)(op + (size_t)(2 * q + 1) * (OH * OW)) = v1;
        }
    }
}

extern "C" void kernel_launch(void* const* d_in, const int* in_sizes, int n_in,
                              void* d_out, int out_size) {
    const float* x    = (const float*)d_in[0];
    const float* k    = (const float*)d_in[1];
    const float* bias = (const float*)d_in[2];
    const float* dx   = (const float*)d_in[3];
    const float* dw   = (const float*)d_in[4];
    float* out = (float*)d_out;

    dim3 grid(OH / 2, NB);   // (15, 8) = 120 blocks, <=1 per SM, uniform
    fused_kernel<<<grid, 512>>>(x, k, bias, dx, dw, out);
}